// round 15
// baseline (speedup 1.0000x reference)
#include <cuda_runtime.h>
#include <cuda_bf16.h>
#include <cstdint>
#include <math.h>

#define MODS 3
#define HEADS 4
#define HID 256
#define EMBD 512
#define NN0 49152
#define NN1 16384
#define BB 8192
#define EE0 262144
#define EE1 131072
#define INSZ 50000

#define TSEG (MODS * (NN1 + BB))
#define TEDG (MODS * (EE0 + EE1))
#define NSCANB ((TSEG + 1023) / 1024)

// ---------------- static scratch ----------------
__device__ float g_h[(size_t)MODS * NN0 * HID];
__device__ float g_s[(size_t)MODS * NN0 * HEADS * 2];
__device__ float g_out0[(size_t)MODS * NN1 * HID];
__device__ float g_gat1[(size_t)MODS * BB * HID];
__device__ float g_c[(size_t)MODS * EE0 * HEADS];
__device__ int   g_cnt[TSEG];
__device__ int   g_indptr[TSEG + 1];
__device__ int   g_wp[TSEG];
__device__ int   g_order[TEDG];
__device__ int   g_blksum[NSCANB];
__device__ __nv_bfloat16 g_ehi[(size_t)BB * EMBD];
__device__ __nv_bfloat16 g_elo[(size_t)BB * EMBD];
__device__ __nv_bfloat16 g_pwhi[(size_t)MODS * INSZ * HID];
__device__ __nv_bfloat16 g_pwlo[(size_t)MODS * INSZ * HID];
__device__ __nv_bfloat16 g_wghi[(size_t)MODS * HID * HID];
__device__ __nv_bfloat16 g_wglo[(size_t)MODS * HID * HID];
__device__ __nv_bfloat16 g_ewhi[(size_t)HID * EMBD];
__device__ __nv_bfloat16 g_ewlo[(size_t)HID * EMBD];
__device__ __nv_bfloat16 g_o0hi[(size_t)MODS * NN1 * HID];
__device__ __nv_bfloat16 g_o0lo[(size_t)MODS * NN1 * HID];
__device__ __nv_bfloat16 g_achi[(size_t)BB * HID];
__device__ __nv_bfloat16 g_aclo[(size_t)BB * HID];

// ---------------- split helpers ----------------
__device__ __forceinline__ void split4(float4 v, __nv_bfloat16* hi, __nv_bfloat16* lo,
                                       size_t i) {
    __nv_bfloat16 h0 = __float2bfloat16(v.x), h1 = __float2bfloat16(v.y);
    __nv_bfloat16 h2 = __float2bfloat16(v.z), h3 = __float2bfloat16(v.w);
    *(__nv_bfloat162*)(hi + i) = __nv_bfloat162(h0, h1);
    *(__nv_bfloat162*)(hi + i + 2) = __nv_bfloat162(h2, h3);
    *(__nv_bfloat162*)(lo + i) = __nv_bfloat162(
        __float2bfloat16(v.x - __bfloat162float(h0)),
        __float2bfloat16(v.y - __bfloat162float(h1)));
    *(__nv_bfloat162*)(lo + i + 2) = __nv_bfloat162(
        __float2bfloat16(v.z - __bfloat162float(h2)),
        __float2bfloat16(v.w - __bfloat162float(h3)));
}

// per-mod pre_W + pre_b fused split: x/hi/lo pre-offset to the mod slice
__global__ void k_split_pw(const float* __restrict__ x, const float* __restrict__ b,
                           __nv_bfloat16* __restrict__ hi, __nv_bfloat16* __restrict__ lo) {
    size_t i = ((size_t)blockIdx.x * blockDim.x + threadIdx.x) * 4;
    if (i >= (size_t)INSZ * HID) return;
    int col = (int)(i & (HID - 1));
    float4 v = *(const float4*)(x + i);
    float4 bb = *(const float4*)(b + col);
    v.x += bb.x; v.y += bb.y; v.z += bb.z; v.w += bb.w;
    split4(v, hi, lo, i);
}

__global__ void k_split(const float* __restrict__ x,
                        __nv_bfloat16* __restrict__ hi, __nv_bfloat16* __restrict__ lo,
                        int n) {
    size_t i = ((size_t)blockIdx.x * blockDim.x + threadIdx.x) * 4;
    if (i >= (size_t)n) return;
    split4(*(const float4*)(x + i), hi, lo, i);
}

// ---------------- small utility kernels ----------------
__global__ void k_zero_i(int* p, int n) {
    int i = blockIdx.x * blockDim.x + threadIdx.x;
    if (i < n) p[i] = 0;
}
__global__ void k_hist_all(const int* __restrict__ dst0, const int* __restrict__ dst1,
                           int* cnt) {
    int i = blockIdx.x * blockDim.x + threadIdx.x;
    if (i >= TEDG) return;
    int mod = i / (EE0 + EE1);
    int rem = i - mod * (EE0 + EE1);
    int seg;
    if (rem < EE0) seg = mod * (NN1 + BB) + dst0[(size_t)mod * EE0 + rem];
    else seg = mod * (NN1 + BB) + NN1 + dst1[(size_t)mod * EE1 + (rem - EE0)];
    atomicAdd(&cnt[seg], 1);
}
__global__ void k_scan1(const int* __restrict__ cnt, int n, int* indptr, int* blksum) {
    __shared__ int part[1024];
    int tid = threadIdx.x;
    int i = blockIdx.x * 1024 + tid;
    int v = (i < n) ? cnt[i] : 0;
    part[tid] = v;
    __syncthreads();
    for (int off = 1; off < 1024; off <<= 1) {
        int t = (tid >= off) ? part[tid - off] : 0;
        __syncthreads();
        part[tid] += t;
        __syncthreads();
    }
    if (i < n) indptr[i] = part[tid] - v;
    if (tid == 1023) blksum[blockIdx.x] = part[1023];
}
__global__ void k_scan2(int* blksum, int nb, int* indptr, int n) {
    __shared__ int sh[128];
    int tid = threadIdx.x;
    int v = (tid < nb) ? blksum[tid] : 0;
    sh[tid] = v;
    __syncthreads();
    for (int off = 1; off < 128; off <<= 1) {
        int t = (tid >= off) ? sh[tid - off] : 0;
        __syncthreads();
        sh[tid] += t;
        __syncthreads();
    }
    if (tid < nb) blksum[tid] = sh[tid] - v;
    if (tid == 127) indptr[n] = sh[127];
}
__global__ void k_scan3(int* indptr, int* wp, const int* __restrict__ blksum, int n) {
    int i = blockIdx.x * blockDim.x + threadIdx.x;
    if (i < n) {
        int v = indptr[i] + blksum[i >> 10];
        indptr[i] = v;
        wp[i] = v;
    }
}
__global__ void k_scatter_all(const int* __restrict__ dst0, const int* __restrict__ dst1,
                              int* wp, int* order) {
    int i = blockIdx.x * blockDim.x + threadIdx.x;
    if (i >= TEDG) return;
    int mod = i / (EE0 + EE1);
    int rem = i - mod * (EE0 + EE1);
    int seg, loc;
    if (rem < EE0) {
        loc = rem;
        seg = mod * (NN1 + BB) + dst0[(size_t)mod * EE0 + rem];
    } else {
        loc = rem - EE0;
        seg = mod * (NN1 + BB) + NN1 + dst1[(size_t)mod * EE1 + loc];
    }
    int p = atomicAdd(&wp[seg], 1);
    order[p] = loc;
}
__global__ void k_sortseg(const int* __restrict__ indptr, int nseg, int* order) {
    int j = blockIdx.x * blockDim.x + threadIdx.x;
    if (j >= nseg) return;
    int b = indptr[j], e = indptr[j + 1];
    for (int i = b + 1; i < e; i++) {
        int v = order[i];
        int k = i - 1;
        while (k >= b && order[k] > v) { order[k + 1] = order[k]; k--; }
        order[k + 1] = v;
    }
}

__device__ __forceinline__ float lrelu(float x) { return x > 0.f ? x : 0.2f * x; }

// 2-slot score layout: s[(row*HEADS + head)*2 + slot]
__device__ __forceinline__ float4 load_score(const float* __restrict__ s, int row) {
    const float4* sp = (const float4*)(s + (size_t)row * 8);
    float4 a = sp[0], b = sp[1];
    return make_float4(a.x + a.y, a.z + a.w, b.x + b.y, b.z + b.w);
}

__global__ void k_coef(const int* __restrict__ order, const int* __restrict__ indptr,
                       const int* __restrict__ src, const float* __restrict__ vals,
                       const float* __restrict__ s, float* __restrict__ c, int nseg) {
    int w = (blockIdx.x * blockDim.x + threadIdx.x) >> 5;
    int lane = threadIdx.x & 31;
    if (w >= nseg) return;
    int beg = indptr[w], end = indptr[w + 1];
    int cnt = end - beg;
    if (cnt == 0) return;

    if (cnt <= 32) {
        bool act = lane < cnt;
        int e = 0;
        float4 sv = make_float4(0.f, 0.f, 0.f, 0.f);
        float v = 0.f;
        if (act) {
            e = order[beg + lane];
            sv = load_score(s, src[e]);
            v = vals[e];
        }
        float l0 = act ? lrelu(sv.x) : -1e30f;
        float l1 = act ? lrelu(sv.y) : -1e30f;
        float l2 = act ? lrelu(sv.z) : -1e30f;
        float l3 = act ? lrelu(sv.w) : -1e30f;
        float m0 = l0, m1 = l1, m2 = l2, m3 = l3;
        for (int off = 16; off; off >>= 1) {
            m0 = fmaxf(m0, __shfl_xor_sync(0xffffffffu, m0, off));
            m1 = fmaxf(m1, __shfl_xor_sync(0xffffffffu, m1, off));
            m2 = fmaxf(m2, __shfl_xor_sync(0xffffffffu, m2, off));
            m3 = fmaxf(m3, __shfl_xor_sync(0xffffffffu, m3, off));
        }
        float e0 = act ? expf(l0 - m0) : 0.f;
        float e1 = act ? expf(l1 - m1) : 0.f;
        float e2 = act ? expf(l2 - m2) : 0.f;
        float e3 = act ? expf(l3 - m3) : 0.f;
        float d0 = e0, d1 = e1, d2 = e2, d3 = e3;
        for (int off = 16; off; off >>= 1) {
            d0 += __shfl_xor_sync(0xffffffffu, d0, off);
            d1 += __shfl_xor_sync(0xffffffffu, d1, off);
            d2 += __shfl_xor_sync(0xffffffffu, d2, off);
            d3 += __shfl_xor_sync(0xffffffffu, d3, off);
        }
        if (act) {
            float4 cc;
            cc.x = e0 / (d0 + 1e-16f) * v;
            cc.y = e1 / (d1 + 1e-16f) * v;
            cc.z = e2 / (d2 + 1e-16f) * v;
            cc.w = e3 / (d3 + 1e-16f) * v;
            *(float4*)(c + (size_t)e * 4) = cc;
        }
        return;
    }

    float m0 = -1e30f, m1 = -1e30f, m2 = -1e30f, m3 = -1e30f;
    for (int p = beg + lane; p < end; p += 32) {
        int e = order[p];
        float4 sv = load_score(s, src[e]);
        m0 = fmaxf(m0, lrelu(sv.x)); m1 = fmaxf(m1, lrelu(sv.y));
        m2 = fmaxf(m2, lrelu(sv.z)); m3 = fmaxf(m3, lrelu(sv.w));
    }
    for (int off = 16; off; off >>= 1) {
        m0 = fmaxf(m0, __shfl_xor_sync(0xffffffffu, m0, off));
        m1 = fmaxf(m1, __shfl_xor_sync(0xffffffffu, m1, off));
        m2 = fmaxf(m2, __shfl_xor_sync(0xffffffffu, m2, off));
        m3 = fmaxf(m3, __shfl_xor_sync(0xffffffffu, m3, off));
    }
    float d0 = 0.f, d1 = 0.f, d2 = 0.f, d3 = 0.f;
    for (int p = beg + lane; p < end; p += 32) {
        int e = order[p];
        float4 sv = load_score(s, src[e]);
        d0 += expf(lrelu(sv.x) - m0); d1 += expf(lrelu(sv.y) - m1);
        d2 += expf(lrelu(sv.z) - m2); d3 += expf(lrelu(sv.w) - m3);
    }
    for (int off = 16; off; off >>= 1) {
        d0 += __shfl_xor_sync(0xffffffffu, d0, off);
        d1 += __shfl_xor_sync(0xffffffffu, d1, off);
        d2 += __shfl_xor_sync(0xffffffffu, d2, off);
        d3 += __shfl_xor_sync(0xffffffffu, d3, off);
    }
    float i0 = 1.f / (d0 + 1e-16f), i1 = 1.f / (d1 + 1e-16f);
    float i2 = 1.f / (d2 + 1e-16f), i3 = 1.f / (d3 + 1e-16f);
    for (int p = beg + lane; p < end; p += 32) {
        int e = order[p];
        float4 sv = load_score(s, src[e]);
        float v = vals[e];
        float4 cc;
        cc.x = expf(lrelu(sv.x) - m0) * i0 * v;
        cc.y = expf(lrelu(sv.y) - m1) * i1 * v;
        cc.z = expf(lrelu(sv.z) - m2) * i2 * v;
        cc.w = expf(lrelu(sv.w) - m3) * i3 * v;
        *(float4*)(c + (size_t)e * 4) = cc;
    }
}

// reduce; optionally emits bf16 hi/lo split of the output
__global__ void k_reduce(const int* __restrict__ order, const int* __restrict__ indptr,
                         const int* __restrict__ src, const float* __restrict__ c,
                         const float* __restrict__ h, const float* __restrict__ bias,
                         float* __restrict__ out,
                         __nv_bfloat16* __restrict__ ohi, __nv_bfloat16* __restrict__ olo) {
    int j = blockIdx.x;
    int t = threadIdx.x;
    int head = t >> 6;
    __shared__ int ssrc[64];
    __shared__ float scoef[64 * 4];
    int beg = indptr[j], end = indptr[j + 1];
    float acc = 0.f;
    for (int ch = beg; ch < end; ch += 64) {
        int n = min(64, end - ch);
        if (t < n) {
            int e = order[ch + t];
            ssrc[t] = src[e];
            *(float4*)&scoef[t * 4] = *(const float4*)(c + (size_t)e * 4);
        }
        __syncthreads();
        for (int q = 0; q < n; q++)
            acc += scoef[q * 4 + head] * h[(size_t)ssrc[q] * HID + t];
        __syncthreads();
    }
    float r = acc + bias[t];
    size_t p = (size_t)j * HID + t;
    out[p] = r;
    if (ohi) {
        __nv_bfloat16 hb = __float2bfloat16(r);
        ohi[p] = hb;
        olo[p] = __float2bfloat16(r - __bfloat162float(hb));
    }
}

// ---------------- bf16 mma machinery ----------------
#define DSTRIDE 24
#define BPAD 136

#define LDSM4(R, ADDR)                                                        \
    asm volatile("ldmatrix.sync.aligned.m8n8.x4.shared.b16 {%0,%1,%2,%3}, [%4];" \
                 : "=r"((R)[0]), "=r"((R)[1]), "=r"((R)[2]), "=r"((R)[3])     \
                 : "r"(ADDR))
#define LDSM4T(R, ADDR)                                                       \
    asm volatile("ldmatrix.sync.aligned.m8n8.x4.trans.shared.b16 {%0,%1,%2,%3}, [%4];" \
                 : "=r"((R)[0]), "=r"((R)[1]), "=r"((R)[2]), "=r"((R)[3])     \
                 : "r"(ADDR))
#define MMA16816(C, A, B0, B1)                                                \
    asm volatile(                                                             \
        "mma.sync.aligned.m16n8k16.row.col.f32.bf16.bf16.f32 "                \
        "{%0,%1,%2,%3},{%4,%5,%6,%7},{%8,%9},{%0,%1,%2,%3};"                  \
        : "+f"((C)[0]), "+f"((C)[1]), "+f"((C)[2]), "+f"((C)[3])              \
        : "r"((A)[0]), "r"((A)[1]), "r"((A)[2]), "r"((A)[3]), "r"(B0), "r"(B1))

// pure-bf16 GEMM with optional fused score (2-slot plain stores, no atomics).
__global__ __launch_bounds__(512) void k_gemm_bf(
    const __nv_bfloat16* __restrict__ Ahi, const __nv_bfloat16* __restrict__ Alo,
    const int* __restrict__ gidx,
    const __nv_bfloat16* __restrict__ Bhi, const __nv_bfloat16* __restrict__ Blo,
    const float* __restrict__ cbias,
    float* __restrict__ C, int M, int N, int K,
    __nv_bfloat16* __restrict__ ohi, __nv_bfloat16* __restrict__ olo,
    const float* __restrict__ att, float* __restrict__ sout) {
    __shared__ __nv_bfloat16 sA[2][2][128 * DSTRIDE];
    __shared__ __nv_bfloat16 sB[2][2][16 * BPAD];
    int tid = threadIdx.x;
    int lane = tid & 31, wid = tid >> 5;
    int wm = wid >> 2, wn = wid & 3;
    int bm = blockIdx.y * 128, bn = blockIdx.x * 128;

    int arow = tid >> 2;
    int acol = (tid & 3) * 4;
    size_t abase = (size_t)(gidx ? gidx[bm + arow] : (bm + arow)) * K + acol;
    int asoff = arow * DSTRIDE + acol;
    int bkrow = tid >> 5;
    int bncol = (tid & 31) * 4;
    int bsoff = bkrow * BPAD + bncol;

    int alrow = (lane & 7) + ((lane >> 3) & 1) * 8;
    int alcol = (lane >> 4) * 8;
    int blrow = lane & 15;
    int blcol = (lane >> 4) * 8;

    float acc[2][4][4];
#pragma unroll
    for (int m = 0; m < 2; m++)
#pragma unroll
        for (int n = 0; n < 4; n++)
#pragma unroll
            for (int q = 0; q < 4; q++) acc[m][n][q] = 0.f;

    int niter = K / 16;

    {
        uint2 ah = *(const uint2*)(Ahi + abase);
        uint2 al = *(const uint2*)(Alo + abase);
        uint2 bh = *(const uint2*)(Bhi + (size_t)bkrow * N + bn + bncol);
        uint2 bl = *(const uint2*)(Blo + (size_t)bkrow * N + bn + bncol);
        *(uint2*)&sA[0][0][asoff] = ah;
        *(uint2*)&sA[0][1][asoff] = al;
        *(uint2*)&sB[0][0][bsoff] = bh;
        *(uint2*)&sB[0][1][bsoff] = bl;
    }
    uint2 avh = *(const uint2*)(Ahi + abase + 16);
    uint2 avl = *(const uint2*)(Alo + abase + 16);
    uint2 bvh = *(const uint2*)(Bhi + (size_t)(16 + bkrow) * N + bn + bncol);
    uint2 bvl = *(const uint2*)(Blo + (size_t)(16 + bkrow) * N + bn + bncol);
    __syncthreads();

    for (int it = 0; it < niter; it++) {
        int st = it & 1;
        uint32_t fa[2][2][4], fb[2][2][4];
#pragma unroll
        for (int mt = 0; mt < 2; mt++)
#pragma unroll
            for (int op = 0; op < 2; op++) {
                uint32_t ad = (uint32_t)__cvta_generic_to_shared(
                    &sA[st][op][(wm * 32 + mt * 16 + alrow) * DSTRIDE + alcol]);
                LDSM4(fa[mt][op], ad);
            }
#pragma unroll
        for (int np = 0; np < 2; np++)
#pragma unroll
            for (int op = 0; op < 2; op++) {
                uint32_t ad = (uint32_t)__cvta_generic_to_shared(
                    &sB[st][op][blrow * BPAD + wn * 32 + np * 16 + blcol]);
                LDSM4T(fb[np][op], ad);
            }
        if (it + 1 < niter) {
            int ns = st ^ 1;
            *(uint2*)&sA[ns][0][asoff] = avh;
            *(uint2*)&sA[ns][1][asoff] = avl;
            *(uint2*)&sB[ns][0][bsoff] = bvh;
            *(uint2*)&sB[ns][1][bsoff] = bvl;
        }
        __syncthreads();
        if (it + 2 < niter) {
            avh = *(const uint2*)(Ahi + abase + (size_t)(it + 2) * 16);
            avl = *(const uint2*)(Alo + abase + (size_t)(it + 2) * 16);
            bvh = *(const uint2*)(Bhi + (size_t)((it + 2) * 16 + bkrow) * N + bn + bncol);
            bvl = *(const uint2*)(Blo + (size_t)((it + 2) * 16 + bkrow) * N + bn + bncol);
        }
#pragma unroll
        for (int mt = 0; mt < 2; mt++)
#pragma unroll
            for (int np = 0; np < 2; np++)
#pragma unroll
                for (int s = 0; s < 2; s++) {
                    int nt = np * 2 + s;
                    MMA16816(acc[mt][nt], fa[mt][0], fb[np][0][2 * s], fb[np][0][2 * s + 1]);
                    MMA16816(acc[mt][nt], fa[mt][0], fb[np][1][2 * s], fb[np][1][2 * s + 1]);
                    MMA16816(acc[mt][nt], fa[mt][1], fb[np][0][2 * s], fb[np][0][2 * s + 1]);
                }
    }

#pragma unroll
    for (int mt = 0; mt < 2; mt++) {
        int r0 = bm + wm * 32 + mt * 16 + (lane >> 2);
#pragma unroll
        for (int nt = 0; nt < 4; nt++) {
            int cc = bn + wn * 32 + nt * 8 + (lane & 3) * 2;
            float2 v0 = {acc[mt][nt][0], acc[mt][nt][1]};
            float2 v1 = {acc[mt][nt][2], acc[mt][nt][3]};
            if (cbias) {
                float cb0 = cbias[cc], cb1 = cbias[cc + 1];
                v0.x += cb0; v0.y += cb1;
                v1.x += cb0; v1.y += cb1;
            }
            size_t p0 = (size_t)r0 * N + cc;
            size_t p1 = (size_t)(r0 + 8) * N + cc;
            *(float2*)(C + p0) = v0;
            *(float2*)(C + p1) = v1;
            if (ohi) {
                __nv_bfloat16 a0 = __float2bfloat16(v0.x), a1 = __float2bfloat16(v0.y);
                __nv_bfloat16 b0 = __float2bfloat16(v1.x), b1 = __float2bfloat16(v1.y);
                *(__nv_bfloat162*)(ohi + p0) = __nv_bfloat162(a0, a1);
                *(__nv_bfloat162*)(ohi + p1) = __nv_bfloat162(b0, b1);
                *(__nv_bfloat162*)(olo + p0) = __nv_bfloat162(
                    __float2bfloat16(v0.x - __bfloat162float(a0)),
                    __float2bfloat16(v0.y - __bfloat162float(a1)));
                *(__nv_bfloat162*)(olo + p1) = __nv_bfloat162(
                    __float2bfloat16(v1.x - __bfloat162float(b0)),
                    __float2bfloat16(v1.y - __bfloat162float(b1)));
            }
        }
    }

    // fused score: warp covers one head-half; slot = wn&1, head = bx*2 + (wn>>1).
    if (att) {
        int head = blockIdx.x * 2 + (wn >> 1);
        int slot = wn & 1;
        float av[4][2];
#pragma unroll
        for (int nt = 0; nt < 4; nt++) {
            int cc = bn + wn * 32 + nt * 8 + (lane & 3) * 2;
            av[nt][0] = att[cc];
            av[nt][1] = att[cc + 1];
        }
#pragma unroll
        for (int mt = 0; mt < 2; mt++) {
#pragma unroll
            for (int half = 0; half < 2; half++) {
                float part = 0.f;
#pragma unroll
                for (int nt = 0; nt < 4; nt++)
                    part += acc[mt][nt][half * 2] * av[nt][0] +
                            acc[mt][nt][half * 2 + 1] * av[nt][1];
                part += __shfl_xor_sync(0xffffffffu, part, 1);
                part += __shfl_xor_sync(0xffffffffu, part, 2);
                if ((lane & 3) == 0) {
                    int row = bm + wm * 32 + mt * 16 + (lane >> 2) + half * 8;
                    sout[((size_t)row * HEADS + head) * 2 + slot] = part;
                }
            }
        }
    }
}

// ---------------- NT GEMM via bf16x3 mma, symmetric (R6-proven) ----------------
__global__ __launch_bounds__(512) void k_dot_mma(
    const __nv_bfloat16* __restrict__ Ehi, const __nv_bfloat16* __restrict__ Elo,
    float* __restrict__ C) {
    __shared__ __nv_bfloat16 sA[2][2][128 * DSTRIDE];
    __shared__ __nv_bfloat16 sB[2][2][128 * DSTRIDE];
    int tid = threadIdx.x;
    int lane = tid & 31, wid = tid >> 5;
    int wm = wid >> 2, wn = wid & 3;

    int bid = blockIdx.x;
    int brow = (int)((sqrtf(8.0f * (float)bid + 1.0f) - 1.0f) * 0.5f);
    while ((brow + 1) * (brow + 2) / 2 <= bid) brow++;
    while (brow * (brow + 1) / 2 > bid) brow--;
    int bcol = bid - brow * (brow + 1) / 2;
    int bi = brow * 128, bj = bcol * 128;  // bi >= bj

    int grow = tid >> 2;
    int gcol = (tid & 3) * 4;
    const __nv_bfloat16* pAhi = Ehi + (size_t)(bi + grow) * EMBD + gcol;
    const __nv_bfloat16* pAlo = Elo + (size_t)(bi + grow) * EMBD + gcol;
    const __nv_bfloat16* pBhi = Ehi + (size_t)(bj + grow) * EMBD + gcol;
    const __nv_bfloat16* pBlo = Elo + (size_t)(bj + grow) * EMBD + gcol;
    int soff = grow * DSTRIDE + gcol;

    int lrow = (lane & 7) + ((lane >> 3) & 1) * 8;
    int lcol = (lane >> 4) * 8;

    float acc[2][4][4];
#pragma unroll
    for (int m = 0; m < 2; m++)
#pragma unroll
        for (int n = 0; n < 4; n++)
#pragma unroll
            for (int q = 0; q < 4; q++) acc[m][n][q] = 0.f;

    uint2 vah = *(const uint2*)pAhi;
    uint2 val = *(const uint2*)pAlo;
    uint2 vbh = *(const uint2*)pBhi;
    uint2 vbl = *(const uint2*)pBlo;
    *(uint2*)&sA[0][0][soff] = vah;
    *(uint2*)&sA[0][1][soff] = val;
    *(uint2*)&sB[0][0][soff] = vbh;
    *(uint2*)&sB[0][1][soff] = vbl;
    vah = *(const uint2*)(pAhi + 16);
    val = *(const uint2*)(pAlo + 16);
    vbh = *(const uint2*)(pBhi + 16);
    vbl = *(const uint2*)(pBlo + 16);
    __syncthreads();

    for (int it = 0; it < EMBD / 16; it++) {
        int st = it & 1;
        uint32_t fa[2][2][4], fb[2][2][4];
#pragma unroll
        for (int mt = 0; mt < 2; mt++)
#pragma unroll
            for (int op = 0; op < 2; op++) {
                uint32_t ad = (uint32_t)__cvta_generic_to_shared(
                    &sA[st][op][(wm * 32 + mt * 16 + lrow) * DSTRIDE + lcol]);
                LDSM4(fa[mt][op], ad);
            }
#pragma unroll
        for (int np = 0; np < 2; np++)
#pragma unroll
            for (int op = 0; op < 2; op++) {
                uint32_t ad = (uint32_t)__cvta_generic_to_shared(
                    &sB[st][op][(wn * 32 + np * 16 + lrow) * DSTRIDE + lcol]);
                LDSM4(fb[np][op], ad);
            }
        if (it < EMBD / 16 - 1) {
            int ns = st ^ 1;
            *(uint2*)&sA[ns][0][soff] = vah;
            *(uint2*)&sA[ns][1][soff] = val;
            *(uint2*)&sB[ns][0][soff] = vbh;
            *(uint2*)&sB[ns][1][soff] = vbl;
        }
        __syncthreads();
        if (it < EMBD / 16 - 2) {
            vah = *(const uint2*)(pAhi + (it + 2) * 16);
            val = *(const uint2*)(pAlo + (it + 2) * 16);
            vbh = *(const uint2*)(pBhi + (it + 2) * 16);
            vbl = *(const uint2*)(pBlo + (it + 2) * 16);
        }
#pragma unroll
        for (int mt = 0; mt < 2; mt++)
#pragma unroll
            for (int np = 0; np < 2; np++)
#pragma unroll
                for (int s = 0; s < 2; s++) {
                    int nt = np * 2 + s;
                    MMA16816(acc[mt][nt], fa[mt][0], fb[np][0][s], fb[np][0][2 + s]);
                    MMA16816(acc[mt][nt], fa[mt][0], fb[np][1][s], fb[np][1][2 + s]);
                    MMA16816(acc[mt][nt], fa[mt][1], fb[np][0][s], fb[np][0][2 + s]);
                }
    }

#pragma unroll
    for (int mt = 0; mt < 2; mt++) {
        int r0 = bi + wm * 32 + mt * 16 + (lane >> 2);
#pragma unroll
        for (int nt = 0; nt < 4; nt++) {
            int cc = bj + wn * 32 + nt * 8 + (lane & 3) * 2;
            float2 v0 = {acc[mt][nt][0], acc[mt][nt][1]};
            float2 v1 = {acc[mt][nt][2], acc[mt][nt][3]};
            *(float2*)(C + (size_t)r0 * BB + cc) = v0;
            *(float2*)(C + (size_t)(r0 + 8) * BB + cc) = v1;
            if (bi != bj) {
                C[(size_t)cc * BB + r0] = acc[mt][nt][0];
                C[(size_t)(cc + 1) * BB + r0] = acc[mt][nt][1];
                C[(size_t)cc * BB + r0 + 8] = acc[mt][nt][2];
                C[(size_t)(cc + 1) * BB + r0 + 8] = acc[mt][nt][3];
            }
        }
    }
}

// all-mods skip + interpolation accumulate -> bf16 hi/lo; also writes weights out
__global__ void k_accum_all(const float* __restrict__ out0, size_t strO,
                            const int* __restrict__ res,
                            const float* __restrict__ gat1, size_t strG,
                            const float* __restrict__ masks,
                            const float* __restrict__ iw,
                            __nv_bfloat16* __restrict__ ahi,
                            __nv_bfloat16* __restrict__ alo,
                            float* __restrict__ wout) {
    int b = blockIdx.x;
    int t = threadIdx.x;
    __shared__ float coef[MODS];
    __shared__ int rid[MODS];
    if (t < MODS) {
        float w0 = iw[0], w1 = iw[1], w2 = iw[2];
        float mw = fmaxf(w0, fmaxf(w1, w2));
        float e0 = expf(w0 - mw), e1 = expf(w1 - mw), e2 = expf(w2 - mw);
        float ws = e0 + e1 + e2;
        float wi = (t == 0 ? e0 : (t == 1 ? e1 : e2)) / ws;
        if (b == 0) wout[t] = wi;  // weights output (block 0 only)
        float m0 = masks[b * 3 + 0], m1 = masks[b * 3 + 1], m2 = masks[b * 3 + 2];
        float msum = m0 + m1 + m2;
        float r = 1.0f + 1.0f / powf(4.0f, 20.0f) + 1.0f / powf(msum, 20.0f);
        r = floorf(r);
        r = r / (r + 1e-10f);
        float z0 = m0 * r, z1 = m1 * r, z2 = m2 * r;
        z0 = z0 + (1.0f - z0) * (-1e10f);
        z1 = z1 + (1.0f - z1) * (-1e10f);
        z2 = z2 + (1.0f - z2) * (-1e10f);
        float zm = fmaxf(z0, fmaxf(z1, z2));
        float x0 = expf(z0 - zm), x1 = expf(z1 - zm), x2 = expf(z2 - zm);
        float xs = x0 + x1 + x2;
        float im = (t == 0 ? x0 : (t == 1 ? x1 : x2)) / xs;
        coef[t] = wi * im;
        rid[t] = res[(size_t)t * BB + b];
    }
    __syncthreads();
    float v = 0.f;
#pragma unroll
    for (int m = 0; m < MODS; m++)
        v += coef[m] * (out0[(size_t)m * strO + (size_t)rid[m] * HID + t] +
                        gat1[(size_t)m * strG + (size_t)b * HID + t]);
    size_t p = (size_t)b * HID + t;
    __nv_bfloat16 hb = __float2bfloat16(v);
    ahi[p] = hb;
    alo[p] = __float2bfloat16(v - __bfloat162float(hb));
}

extern "C" void kernel_launch(void* const* d_in, const int* in_sizes, int n_in,
                              void* d_out, int out_size) {
    const int*   n_id     = (const int*)d_in[0];
    const int*   src0     = (const int*)d_in[1];
    const int*   dst0     = (const int*)d_in[2];
    const int*   src1     = (const int*)d_in[3];
    const int*   dst1     = (const int*)d_in[4];
    const int*   res_n_id = (const int*)d_in[5];
    const float* vals0    = (const float*)d_in[6];
    const float* vals1    = (const float*)d_in[7];
    const float* masks    = (const float*)d_in[8];
    const float* pre_W    = (const float*)d_in[9];
    const float* pre_b    = (const float*)d_in[10];
    const float* W_gat    = (const float*)d_in[11];
    const float* att      = (const float*)d_in[12];
    const float* gat_b    = (const float*)d_in[13];
    const float* interp_w = (const float*)d_in[14];
    const float* emb_W    = (const float*)d_in[15];
    const float* emb_b    = (const float*)d_in[16];

    float* dot = (float*)d_out;
    float* emb = dot + (size_t)BB * BB;
    float* wout = emb + (size_t)BB * EMBD;

    float *h, *s, *out0, *gat1, *c;
    int *cnt, *indptr, *wp, *order, *blksum;
    __nv_bfloat16 *ehi, *elo, *pwhi, *pwlo, *wghi, *wglo, *ewhi, *ewlo;
    __nv_bfloat16 *o0hi, *o0lo, *achi, *aclo;
    cudaGetSymbolAddress((void**)&h, g_h);
    cudaGetSymbolAddress((void**)&s, g_s);
    cudaGetSymbolAddress((void**)&out0, g_out0);
    cudaGetSymbolAddress((void**)&gat1, g_gat1);
    cudaGetSymbolAddress((void**)&c, g_c);
    cudaGetSymbolAddress((void**)&cnt, g_cnt);
    cudaGetSymbolAddress((void**)&indptr, g_indptr);
    cudaGetSymbolAddress((void**)&wp, g_wp);
    cudaGetSymbolAddress((void**)&order, g_order);
    cudaGetSymbolAddress((void**)&blksum, g_blksum);
    cudaGetSymbolAddress((void**)&ehi, g_ehi);
    cudaGetSymbolAddress((void**)&elo, g_elo);
    cudaGetSymbolAddress((void**)&pwhi, g_pwhi);
    cudaGetSymbolAddress((void**)&pwlo, g_pwlo);
    cudaGetSymbolAddress((void**)&wghi, g_wghi);
    cudaGetSymbolAddress((void**)&wglo, g_wglo);
    cudaGetSymbolAddress((void**)&ewhi, g_ewhi);
    cudaGetSymbolAddress((void**)&ewlo, g_ewlo);
    cudaGetSymbolAddress((void**)&o0hi, g_o0hi);
    cudaGetSymbolAddress((void**)&o0lo, g_o0lo);
    cudaGetSymbolAddress((void**)&achi, g_achi);
    cudaGetSymbolAddress((void**)&aclo, g_aclo);

    // ---- streams/events: created AND destroyed within this call ----
    cudaStream_t st[MODS], stCSR;
    st[0] = 0;  // legacy stream (capture origin)
    cudaStreamCreateWithFlags(&st[1], cudaStreamNonBlocking);
    cudaStreamCreateWithFlags(&st[2], cudaStreamNonBlocking);
    cudaStreamCreateWithFlags(&stCSR, cudaStreamNonBlocking);
    cudaEvent_t evW, evCSR, evEW, evJoin1, evJoin2;
    cudaEventCreateWithFlags(&evW, cudaEventDisableTiming);
    cudaEventCreateWithFlags(&evCSR, cudaEventDisableTiming);
    cudaEventCreateWithFlags(&evEW, cudaEventDisableTiming);
    cudaEventCreateWithFlags(&evJoin1, cudaEventDisableTiming);
    cudaEventCreateWithFlags(&evJoin2, cudaEventDisableTiming);

    // tiny W_gat split first (all chains need it), then fork everything
    k_split<<<(MODS * HID * HID / 4 + 255) / 256, 256>>>(W_gat, wghi, wglo,
                                                         MODS * HID * HID);
    cudaEventRecord(evW, 0);
    cudaStreamWaitEvent(st[1], evW, 0);
    cudaStreamWaitEvent(st[2], evW, 0);
    cudaStreamWaitEvent(stCSR, evW, 0);

    // ---- CSR build + emb_W split on stCSR (overlaps chains) ----
    k_zero_i<<<(TSEG + 255) / 256, 256, 0, stCSR>>>(cnt, TSEG);
    k_hist_all<<<(TEDG + 255) / 256, 256, 0, stCSR>>>(dst0, dst1, cnt);
    k_scan1<<<NSCANB, 1024, 0, stCSR>>>(cnt, TSEG, indptr, blksum);
    k_scan2<<<1, 128, 0, stCSR>>>(blksum, NSCANB, indptr, TSEG);
    k_scan3<<<(TSEG + 255) / 256, 256, 0, stCSR>>>(indptr, wp, blksum, TSEG);
    k_scatter_all<<<(TEDG + 255) / 256, 256, 0, stCSR>>>(dst0, dst1, wp, order);
    k_sortseg<<<(TSEG + 255) / 256, 256, 0, stCSR>>>(indptr, TSEG, order);
    cudaEventRecord(evCSR, stCSR);
    k_split<<<(HID * EMBD / 4 + 255) / 256, 256, 0, stCSR>>>(emb_W, ewhi, ewlo,
                                                             HID * EMBD);
    cudaEventRecord(evEW, stCSR);

    // ---- 3 modality chains, each prefixed by its own pre_W split ----
    const unsigned pwblk = (unsigned)(((size_t)INSZ * HID / 4 + 255) / 256);
    for (int i = 0; i < MODS; i++) {
        cudaStream_t sm = st[i];
        const float* ai  = att + (size_t)i * HID;
        const float* gbi = gat_b + (size_t)i * HID;
        const int* ip0 = indptr + i * (NN1 + BB);
        const int* ip1 = indptr + i * (NN1 + BB) + NN1;
        float* h_i = h + (size_t)i * NN0 * HID;
        float* s_i = s + (size_t)i * NN0 * HEADS * 2;
        float* c_i = c + (size_t)i * EE0 * HEADS;
        float* out0_i = out0 + (size_t)i * NN1 * HID;
        float* gat1_i = gat1 + (size_t)i * BB * HID;
        const __nv_bfloat16* wghi_i = wghi + (size_t)i * HID * HID;
        const __nv_bfloat16* wglo_i = wglo + (size_t)i * HID * HID;

        // per-mod pre_W split on this chain's stream
        k_split_pw<<<pwblk, 256, 0, sm>>>(pre_W + (size_t)i * INSZ * HID,
                                          pre_b + (size_t)i * HID,
                                          pwhi + (size_t)i * INSZ * HID,
                                          pwlo + (size_t)i * INSZ * HID);

        // block 0
        const int* s0 = src0 + (size_t)i * EE0;
        {
            dim3 grid(HID / 128, NN0 / 128);
            k_gemm_bf<<<grid, 512, 0, sm>>>(pwhi + (size_t)i * INSZ * HID,
                                            pwlo + (size_t)i * INSZ * HID,
                                            n_id + (size_t)i * NN0,
                                            wghi_i, wglo_i, nullptr, h_i,
                                            NN0, HID, HID, nullptr, nullptr, ai, s_i);
        }
        cudaStreamWaitEvent(sm, evCSR, 0);
        k_coef<<<(NN1 * 32 + 255) / 256, 256, 0, sm>>>(
            order, ip0, s0, vals0 + (size_t)i * EE0, s_i, c_i, NN1);
        k_reduce<<<NN1, 256, 0, sm>>>(order, ip0, s0, c_i, h_i, gbi, out0_i,
                                      o0hi + (size_t)i * NN1 * HID,
                                      o0lo + (size_t)i * NN1 * HID);

        // block 1
        const int* s1 = src1 + (size_t)i * EE1;
        {
            dim3 grid(HID / 128, NN1 / 128);
            k_gemm_bf<<<grid, 512, 0, sm>>>(o0hi + (size_t)i * NN1 * HID,
                                            o0lo + (size_t)i * NN1 * HID,
                                            nullptr, wghi_i, wglo_i, nullptr, h_i,
                                            NN1, HID, HID, nullptr, nullptr, ai, s_i);
        }
        k_coef<<<(BB * 32 + 255) / 256, 256, 0, sm>>>(
            order, ip1, s1, vals1 + (size_t)i * EE1, s_i, c_i, BB);
        k_reduce<<<BB, 256, 0, sm>>>(order, ip1, s1, c_i, h_i, gbi, gat1_i,
                                     nullptr, nullptr);
    }

    cudaEventRecord(evJoin1, st[1]);
    cudaEventRecord(evJoin2, st[2]);
    cudaStreamWaitEvent(0, evJoin1, 0);
    cudaStreamWaitEvent(0, evJoin2, 0);
    cudaStreamWaitEvent(0, evEW, 0);

    // skip + interpolation accumulate -> bf16 hi/lo (+ weights output)
    k_accum_all<<<BB, 256>>>(out0, (size_t)NN1 * HID, res_n_id,
                             gat1, (size_t)BB * HID, masks, interp_w,
                             achi, aclo, wout);

    // emb = acc @ emb_W + emb_b (+ fused bf16 hi/lo split of output)
    {
        dim3 grid(EMBD / 128, BB / 128);
        k_gemm_bf<<<grid, 512>>>(achi, aclo, nullptr, ewhi, ewlo, emb_b, emb,
                                 BB, EMBD, HID, ehi, elo, nullptr, nullptr);
    }
    // dot = emb @ emb^T via bf16x3 mma, symmetric half-grid
    {
        int npairs = (BB / 128) * (BB / 128 + 1) / 2;  // 2080
        k_dot_mma<<<npairs, 512>>>(ehi, elo, dot);
    }

    // ---- release fork resources (capture has rejoined stream 0) ----
    cudaEventDestroy(evW);
    cudaEventDestroy(evCSR);
    cudaEventDestroy(evEW);
    cudaEventDestroy(evJoin1);
    cudaEventDestroy(evJoin2);
    cudaStreamDestroy(st[1]);
    cudaStreamDestroy(st[2]);
    cudaStreamDestroy(stCSR);
}

// round 16
// speedup vs baseline: 1.0021x; 1.0021x over previous
#include <cuda_runtime.h>
#include <cuda_bf16.h>
#include <cstdint>
#include <math.h>

#define MODS 3
#define HEADS 4
#define HID 256
#define EMBD 512
#define NN0 49152
#define NN1 16384
#define BB 8192
#define EE0 262144
#define EE1 131072
#define INSZ 50000

#define TSEG (MODS * (NN1 + BB))
#define TEDG (MODS * (EE0 + EE1))
#define NSCANB ((TSEG + 1023) / 1024)

// ---------------- static scratch ----------------
__device__ float g_h[(size_t)MODS * NN0 * HID];
__device__ float g_s[(size_t)MODS * NN0 * HEADS * 2];
__device__ float g_out0[(size_t)MODS * NN1 * HID];
__device__ float g_gat1[(size_t)MODS * BB * HID];
__device__ float g_c[(size_t)MODS * EE0 * HEADS];
__device__ int   g_cnt[TSEG];
__device__ int   g_indptr[TSEG + 1];
__device__ int   g_wp[TSEG];
__device__ int   g_order[TEDG];
__device__ int   g_blksum[NSCANB];
__device__ __nv_bfloat16 g_ehi[(size_t)BB * EMBD];
__device__ __nv_bfloat16 g_elo[(size_t)BB * EMBD];
__device__ __nv_bfloat16 g_pwhi[(size_t)MODS * INSZ * HID];
__device__ __nv_bfloat16 g_pwlo[(size_t)MODS * INSZ * HID];
__device__ __nv_bfloat16 g_wghi[(size_t)MODS * HID * HID];
__device__ __nv_bfloat16 g_wglo[(size_t)MODS * HID * HID];
__device__ __nv_bfloat16 g_ewhi[(size_t)HID * EMBD];
__device__ __nv_bfloat16 g_ewlo[(size_t)HID * EMBD];
__device__ __nv_bfloat16 g_o0hi[(size_t)MODS * NN1 * HID];
__device__ __nv_bfloat16 g_o0lo[(size_t)MODS * NN1 * HID];
__device__ __nv_bfloat16 g_achi[(size_t)BB * HID];
__device__ __nv_bfloat16 g_aclo[(size_t)BB * HID];

// ---------------- split helpers ----------------
__device__ __forceinline__ void split4(float4 v, __nv_bfloat16* hi, __nv_bfloat16* lo,
                                       size_t i) {
    __nv_bfloat16 h0 = __float2bfloat16(v.x), h1 = __float2bfloat16(v.y);
    __nv_bfloat16 h2 = __float2bfloat16(v.z), h3 = __float2bfloat16(v.w);
    *(__nv_bfloat162*)(hi + i) = __nv_bfloat162(h0, h1);
    *(__nv_bfloat162*)(hi + i + 2) = __nv_bfloat162(h2, h3);
    *(__nv_bfloat162*)(lo + i) = __nv_bfloat162(
        __float2bfloat16(v.x - __bfloat162float(h0)),
        __float2bfloat16(v.y - __bfloat162float(h1)));
    *(__nv_bfloat162*)(lo + i + 2) = __nv_bfloat162(
        __float2bfloat16(v.z - __bfloat162float(h2)),
        __float2bfloat16(v.w - __bfloat162float(h3)));
}

__global__ void k_split_pw(const float* __restrict__ x, const float* __restrict__ b,
                           __nv_bfloat16* __restrict__ hi, __nv_bfloat16* __restrict__ lo) {
    size_t i = ((size_t)blockIdx.x * blockDim.x + threadIdx.x) * 4;
    if (i >= (size_t)MODS * INSZ * HID) return;
    int mod = (int)(i / ((size_t)INSZ * HID));
    int col = (int)(i & (HID - 1));
    float4 v = *(const float4*)(x + i);
    float4 bb = *(const float4*)(b + (size_t)mod * HID + col);
    v.x += bb.x; v.y += bb.y; v.z += bb.z; v.w += bb.w;
    split4(v, hi, lo, i);
}

__global__ void k_split(const float* __restrict__ x,
                        __nv_bfloat16* __restrict__ hi, __nv_bfloat16* __restrict__ lo,
                        int n) {
    size_t i = ((size_t)blockIdx.x * blockDim.x + threadIdx.x) * 4;
    if (i >= (size_t)n) return;
    split4(*(const float4*)(x + i), hi, lo, i);
}

// ---------------- small utility kernels ----------------
__global__ void k_zero_i(int* p, int n) {
    int i = blockIdx.x * blockDim.x + threadIdx.x;
    if (i < n) p[i] = 0;
}
__global__ void k_hist_all(const int* __restrict__ dst0, const int* __restrict__ dst1,
                           int* cnt) {
    int i = blockIdx.x * blockDim.x + threadIdx.x;
    if (i >= TEDG) return;
    int mod = i / (EE0 + EE1);
    int rem = i - mod * (EE0 + EE1);
    int seg;
    if (rem < EE0) seg = mod * (NN1 + BB) + dst0[(size_t)mod * EE0 + rem];
    else seg = mod * (NN1 + BB) + NN1 + dst1[(size_t)mod * EE1 + (rem - EE0)];
    atomicAdd(&cnt[seg], 1);
}
__global__ void k_scan1(const int* __restrict__ cnt, int n, int* indptr, int* blksum) {
    __shared__ int part[1024];
    int tid = threadIdx.x;
    int i = blockIdx.x * 1024 + tid;
    int v = (i < n) ? cnt[i] : 0;
    part[tid] = v;
    __syncthreads();
    for (int off = 1; off < 1024; off <<= 1) {
        int t = (tid >= off) ? part[tid - off] : 0;
        __syncthreads();
        part[tid] += t;
        __syncthreads();
    }
    if (i < n) indptr[i] = part[tid] - v;
    if (tid == 1023) blksum[blockIdx.x] = part[1023];
}
__global__ void k_scan2(int* blksum, int nb, int* indptr, int n) {
    __shared__ int sh[128];
    int tid = threadIdx.x;
    int v = (tid < nb) ? blksum[tid] : 0;
    sh[tid] = v;
    __syncthreads();
    for (int off = 1; off < 128; off <<= 1) {
        int t = (tid >= off) ? sh[tid - off] : 0;
        __syncthreads();
        sh[tid] += t;
        __syncthreads();
    }
    if (tid < nb) blksum[tid] = sh[tid] - v;
    if (tid == 127) indptr[n] = sh[127];
}
__global__ void k_scan3(int* indptr, int* wp, const int* __restrict__ blksum, int n) {
    int i = blockIdx.x * blockDim.x + threadIdx.x;
    if (i < n) {
        int v = indptr[i] + blksum[i >> 10];
        indptr[i] = v;
        wp[i] = v;
    }
}
__global__ void k_scatter_all(const int* __restrict__ dst0, const int* __restrict__ dst1,
                              int* wp, int* order) {
    int i = blockIdx.x * blockDim.x + threadIdx.x;
    if (i >= TEDG) return;
    int mod = i / (EE0 + EE1);
    int rem = i - mod * (EE0 + EE1);
    int seg, loc;
    if (rem < EE0) {
        loc = rem;
        seg = mod * (NN1 + BB) + dst0[(size_t)mod * EE0 + rem];
    } else {
        loc = rem - EE0;
        seg = mod * (NN1 + BB) + NN1 + dst1[(size_t)mod * EE1 + loc];
    }
    int p = atomicAdd(&wp[seg], 1);
    order[p] = loc;
}
__global__ void k_sortseg(const int* __restrict__ indptr, int nseg, int* order) {
    int j = blockIdx.x * blockDim.x + threadIdx.x;
    if (j >= nseg) return;
    int b = indptr[j], e = indptr[j + 1];
    for (int i = b + 1; i < e; i++) {
        int v = order[i];
        int k = i - 1;
        while (k >= b && order[k] > v) { order[k + 1] = order[k]; k--; }
        order[k + 1] = v;
    }
}

__device__ __forceinline__ float lrelu(float x) { return x > 0.f ? x : 0.2f * x; }

// 2-slot score layout: s[(row*HEADS + head)*2 + slot]
__device__ __forceinline__ float4 load_score(const float* __restrict__ s, int row) {
    const float4* sp = (const float4*)(s + (size_t)row * 8);
    float4 a = sp[0], b = sp[1];
    return make_float4(a.x + a.y, a.z + a.w, b.x + b.y, b.z + b.w);
}

__global__ void k_coef(const int* __restrict__ order, const int* __restrict__ indptr,
                       const int* __restrict__ src, const float* __restrict__ vals,
                       const float* __restrict__ s, float* __restrict__ c, int nseg) {
    int w = (blockIdx.x * blockDim.x + threadIdx.x) >> 5;
    int lane = threadIdx.x & 31;
    if (w >= nseg) return;
    int beg = indptr[w], end = indptr[w + 1];
    int cnt = end - beg;
    if (cnt == 0) return;

    if (cnt <= 32) {
        bool act = lane < cnt;
        int e = 0;
        float4 sv = make_float4(0.f, 0.f, 0.f, 0.f);
        float v = 0.f;
        if (act) {
            e = order[beg + lane];
            sv = load_score(s, src[e]);
            v = vals[e];
        }
        float l0 = act ? lrelu(sv.x) : -1e30f;
        float l1 = act ? lrelu(sv.y) : -1e30f;
        float l2 = act ? lrelu(sv.z) : -1e30f;
        float l3 = act ? lrelu(sv.w) : -1e30f;
        float m0 = l0, m1 = l1, m2 = l2, m3 = l3;
        for (int off = 16; off; off >>= 1) {
            m0 = fmaxf(m0, __shfl_xor_sync(0xffffffffu, m0, off));
            m1 = fmaxf(m1, __shfl_xor_sync(0xffffffffu, m1, off));
            m2 = fmaxf(m2, __shfl_xor_sync(0xffffffffu, m2, off));
            m3 = fmaxf(m3, __shfl_xor_sync(0xffffffffu, m3, off));
        }
        float e0 = act ? expf(l0 - m0) : 0.f;
        float e1 = act ? expf(l1 - m1) : 0.f;
        float e2 = act ? expf(l2 - m2) : 0.f;
        float e3 = act ? expf(l3 - m3) : 0.f;
        float d0 = e0, d1 = e1, d2 = e2, d3 = e3;
        for (int off = 16; off; off >>= 1) {
            d0 += __shfl_xor_sync(0xffffffffu, d0, off);
            d1 += __shfl_xor_sync(0xffffffffu, d1, off);
            d2 += __shfl_xor_sync(0xffffffffu, d2, off);
            d3 += __shfl_xor_sync(0xffffffffu, d3, off);
        }
        if (act) {
            float4 cc;
            cc.x = e0 / (d0 + 1e-16f) * v;
            cc.y = e1 / (d1 + 1e-16f) * v;
            cc.z = e2 / (d2 + 1e-16f) * v;
            cc.w = e3 / (d3 + 1e-16f) * v;
            *(float4*)(c + (size_t)e * 4) = cc;
        }
        return;
    }

    float m0 = -1e30f, m1 = -1e30f, m2 = -1e30f, m3 = -1e30f;
    for (int p = beg + lane; p < end; p += 32) {
        int e = order[p];
        float4 sv = load_score(s, src[e]);
        m0 = fmaxf(m0, lrelu(sv.x)); m1 = fmaxf(m1, lrelu(sv.y));
        m2 = fmaxf(m2, lrelu(sv.z)); m3 = fmaxf(m3, lrelu(sv.w));
    }
    for (int off = 16; off; off >>= 1) {
        m0 = fmaxf(m0, __shfl_xor_sync(0xffffffffu, m0, off));
        m1 = fmaxf(m1, __shfl_xor_sync(0xffffffffu, m1, off));
        m2 = fmaxf(m2, __shfl_xor_sync(0xffffffffu, m2, off));
        m3 = fmaxf(m3, __shfl_xor_sync(0xffffffffu, m3, off));
    }
    float d0 = 0.f, d1 = 0.f, d2 = 0.f, d3 = 0.f;
    for (int p = beg + lane; p < end; p += 32) {
        int e = order[p];
        float4 sv = load_score(s, src[e]);
        d0 += expf(lrelu(sv.x) - m0); d1 += expf(lrelu(sv.y) - m1);
        d2 += expf(lrelu(sv.z) - m2); d3 += expf(lrelu(sv.w) - m3);
    }
    for (int off = 16; off; off >>= 1) {
        d0 += __shfl_xor_sync(0xffffffffu, d0, off);
        d1 += __shfl_xor_sync(0xffffffffu, d1, off);
        d2 += __shfl_xor_sync(0xffffffffu, d2, off);
        d3 += __shfl_xor_sync(0xffffffffu, d3, off);
    }
    float i0 = 1.f / (d0 + 1e-16f), i1 = 1.f / (d1 + 1e-16f);
    float i2 = 1.f / (d2 + 1e-16f), i3 = 1.f / (d3 + 1e-16f);
    for (int p = beg + lane; p < end; p += 32) {
        int e = order[p];
        float4 sv = load_score(s, src[e]);
        float v = vals[e];
        float4 cc;
        cc.x = expf(lrelu(sv.x) - m0) * i0 * v;
        cc.y = expf(lrelu(sv.y) - m1) * i1 * v;
        cc.z = expf(lrelu(sv.z) - m2) * i2 * v;
        cc.w = expf(lrelu(sv.w) - m3) * i3 * v;
        *(float4*)(c + (size_t)e * 4) = cc;
    }
}

// reduce; optionally emits bf16 hi/lo split of the output
__global__ void k_reduce(const int* __restrict__ order, const int* __restrict__ indptr,
                         const int* __restrict__ src, const float* __restrict__ c,
                         const float* __restrict__ h, const float* __restrict__ bias,
                         float* __restrict__ out,
                         __nv_bfloat16* __restrict__ ohi, __nv_bfloat16* __restrict__ olo) {
    int j = blockIdx.x;
    int t = threadIdx.x;
    int head = t >> 6;
    __shared__ int ssrc[64];
    __shared__ float scoef[64 * 4];
    int beg = indptr[j], end = indptr[j + 1];
    float acc = 0.f;
    for (int ch = beg; ch < end; ch += 64) {
        int n = min(64, end - ch);
        if (t < n) {
            int e = order[ch + t];
            ssrc[t] = src[e];
            *(float4*)&scoef[t * 4] = *(const float4*)(c + (size_t)e * 4);
        }
        __syncthreads();
        for (int q = 0; q < n; q++)
            acc += scoef[q * 4 + head] * h[(size_t)ssrc[q] * HID + t];
        __syncthreads();
    }
    float r = acc + bias[t];
    size_t p = (size_t)j * HID + t;
    out[p] = r;
    if (ohi) {
        __nv_bfloat16 hb = __float2bfloat16(r);
        ohi[p] = hb;
        olo[p] = __float2bfloat16(r - __bfloat162float(hb));
    }
}

// ---------------- bf16 mma machinery ----------------
#define DSTRIDE 24
#define BPAD 136

#define LDSM4(R, ADDR)                                                        \
    asm volatile("ldmatrix.sync.aligned.m8n8.x4.shared.b16 {%0,%1,%2,%3}, [%4];" \
                 : "=r"((R)[0]), "=r"((R)[1]), "=r"((R)[2]), "=r"((R)[3])     \
                 : "r"(ADDR))
#define LDSM4T(R, ADDR)                                                       \
    asm volatile("ldmatrix.sync.aligned.m8n8.x4.trans.shared.b16 {%0,%1,%2,%3}, [%4];" \
                 : "=r"((R)[0]), "=r"((R)[1]), "=r"((R)[2]), "=r"((R)[3])     \
                 : "r"(ADDR))
#define MMA16816(C, A, B0, B1)                                                \
    asm volatile(                                                             \
        "mma.sync.aligned.m16n8k16.row.col.f32.bf16.bf16.f32 "                \
        "{%0,%1,%2,%3},{%4,%5,%6,%7},{%8,%9},{%0,%1,%2,%3};"                  \
        : "+f"((C)[0]), "+f"((C)[1]), "+f"((C)[2]), "+f"((C)[3])              \
        : "r"((A)[0]), "r"((A)[1]), "r"((A)[2]), "r"((A)[3]), "r"(B0), "r"(B1))

// pure-bf16 GEMM with optional fused score (2-slot plain stores, no atomics).
__global__ __launch_bounds__(512) void k_gemm_bf(
    const __nv_bfloat16* __restrict__ Ahi, const __nv_bfloat16* __restrict__ Alo,
    const int* __restrict__ gidx,
    const __nv_bfloat16* __restrict__ Bhi, const __nv_bfloat16* __restrict__ Blo,
    const float* __restrict__ cbias,
    float* __restrict__ C, int M, int N, int K,
    __nv_bfloat16* __restrict__ ohi, __nv_bfloat16* __restrict__ olo,
    const float* __restrict__ att, float* __restrict__ sout) {
    __shared__ __nv_bfloat16 sA[2][2][128 * DSTRIDE];
    __shared__ __nv_bfloat16 sB[2][2][16 * BPAD];
    int tid = threadIdx.x;
    int lane = tid & 31, wid = tid >> 5;
    int wm = wid >> 2, wn = wid & 3;
    int bm = blockIdx.y * 128, bn = blockIdx.x * 128;

    int arow = tid >> 2;
    int acol = (tid & 3) * 4;
    size_t abase = (size_t)(gidx ? gidx[bm + arow] : (bm + arow)) * K + acol;
    int asoff = arow * DSTRIDE + acol;
    int bkrow = tid >> 5;
    int bncol = (tid & 31) * 4;
    int bsoff = bkrow * BPAD + bncol;

    int alrow = (lane & 7) + ((lane >> 3) & 1) * 8;
    int alcol = (lane >> 4) * 8;
    int blrow = lane & 15;
    int blcol = (lane >> 4) * 8;

    float acc[2][4][4];
#pragma unroll
    for (int m = 0; m < 2; m++)
#pragma unroll
        for (int n = 0; n < 4; n++)
#pragma unroll
            for (int q = 0; q < 4; q++) acc[m][n][q] = 0.f;

    int niter = K / 16;

    {
        uint2 ah = *(const uint2*)(Ahi + abase);
        uint2 al = *(const uint2*)(Alo + abase);
        uint2 bh = *(const uint2*)(Bhi + (size_t)bkrow * N + bn + bncol);
        uint2 bl = *(const uint2*)(Blo + (size_t)bkrow * N + bn + bncol);
        *(uint2*)&sA[0][0][asoff] = ah;
        *(uint2*)&sA[0][1][asoff] = al;
        *(uint2*)&sB[0][0][bsoff] = bh;
        *(uint2*)&sB[0][1][bsoff] = bl;
    }
    uint2 avh = *(const uint2*)(Ahi + abase + 16);
    uint2 avl = *(const uint2*)(Alo + abase + 16);
    uint2 bvh = *(const uint2*)(Bhi + (size_t)(16 + bkrow) * N + bn + bncol);
    uint2 bvl = *(const uint2*)(Blo + (size_t)(16 + bkrow) * N + bn + bncol);
    __syncthreads();

    for (int it = 0; it < niter; it++) {
        int st = it & 1;
        uint32_t fa[2][2][4], fb[2][2][4];
#pragma unroll
        for (int mt = 0; mt < 2; mt++)
#pragma unroll
            for (int op = 0; op < 2; op++) {
                uint32_t ad = (uint32_t)__cvta_generic_to_shared(
                    &sA[st][op][(wm * 32 + mt * 16 + alrow) * DSTRIDE + alcol]);
                LDSM4(fa[mt][op], ad);
            }
#pragma unroll
        for (int np = 0; np < 2; np++)
#pragma unroll
            for (int op = 0; op < 2; op++) {
                uint32_t ad = (uint32_t)__cvta_generic_to_shared(
                    &sB[st][op][blrow * BPAD + wn * 32 + np * 16 + blcol]);
                LDSM4T(fb[np][op], ad);
            }
        if (it + 1 < niter) {
            int ns = st ^ 1;
            *(uint2*)&sA[ns][0][asoff] = avh;
            *(uint2*)&sA[ns][1][asoff] = avl;
            *(uint2*)&sB[ns][0][bsoff] = bvh;
            *(uint2*)&sB[ns][1][bsoff] = bvl;
        }
        __syncthreads();
        if (it + 2 < niter) {
            avh = *(const uint2*)(Ahi + abase + (size_t)(it + 2) * 16);
            avl = *(const uint2*)(Alo + abase + (size_t)(it + 2) * 16);
            bvh = *(const uint2*)(Bhi + (size_t)((it + 2) * 16 + bkrow) * N + bn + bncol);
            bvl = *(const uint2*)(Blo + (size_t)((it + 2) * 16 + bkrow) * N + bn + bncol);
        }
#pragma unroll
        for (int mt = 0; mt < 2; mt++)
#pragma unroll
            for (int np = 0; np < 2; np++)
#pragma unroll
                for (int s = 0; s < 2; s++) {
                    int nt = np * 2 + s;
                    MMA16816(acc[mt][nt], fa[mt][0], fb[np][0][2 * s], fb[np][0][2 * s + 1]);
                    MMA16816(acc[mt][nt], fa[mt][0], fb[np][1][2 * s], fb[np][1][2 * s + 1]);
                    MMA16816(acc[mt][nt], fa[mt][1], fb[np][0][2 * s], fb[np][0][2 * s + 1]);
                }
    }

#pragma unroll
    for (int mt = 0; mt < 2; mt++) {
        int r0 = bm + wm * 32 + mt * 16 + (lane >> 2);
#pragma unroll
        for (int nt = 0; nt < 4; nt++) {
            int cc = bn + wn * 32 + nt * 8 + (lane & 3) * 2;
            float2 v0 = {acc[mt][nt][0], acc[mt][nt][1]};
            float2 v1 = {acc[mt][nt][2], acc[mt][nt][3]};
            if (cbias) {
                float cb0 = cbias[cc], cb1 = cbias[cc + 1];
                v0.x += cb0; v0.y += cb1;
                v1.x += cb0; v1.y += cb1;
            }
            size_t p0 = (size_t)r0 * N + cc;
            size_t p1 = (size_t)(r0 + 8) * N + cc;
            *(float2*)(C + p0) = v0;
            *(float2*)(C + p1) = v1;
            if (ohi) {
                __nv_bfloat16 a0 = __float2bfloat16(v0.x), a1 = __float2bfloat16(v0.y);
                __nv_bfloat16 b0 = __float2bfloat16(v1.x), b1 = __float2bfloat16(v1.y);
                *(__nv_bfloat162*)(ohi + p0) = __nv_bfloat162(a0, a1);
                *(__nv_bfloat162*)(ohi + p1) = __nv_bfloat162(b0, b1);
                *(__nv_bfloat162*)(olo + p0) = __nv_bfloat162(
                    __float2bfloat16(v0.x - __bfloat162float(a0)),
                    __float2bfloat16(v0.y - __bfloat162float(a1)));
                *(__nv_bfloat162*)(olo + p1) = __nv_bfloat162(
                    __float2bfloat16(v1.x - __bfloat162float(b0)),
                    __float2bfloat16(v1.y - __bfloat162float(b1)));
            }
        }
    }

    // fused score: warp covers one head-half; slot = wn&1, head = bx*2 + (wn>>1).
    if (att) {
        int head = blockIdx.x * 2 + (wn >> 1);
        int slot = wn & 1;
        float av[4][2];
#pragma unroll
        for (int nt = 0; nt < 4; nt++) {
            int cc = bn + wn * 32 + nt * 8 + (lane & 3) * 2;
            av[nt][0] = att[cc];
            av[nt][1] = att[cc + 1];
        }
#pragma unroll
        for (int mt = 0; mt < 2; mt++) {
#pragma unroll
            for (int half = 0; half < 2; half++) {
                float part = 0.f;
#pragma unroll
                for (int nt = 0; nt < 4; nt++)
                    part += acc[mt][nt][half * 2] * av[nt][0] +
                            acc[mt][nt][half * 2 + 1] * av[nt][1];
                part += __shfl_xor_sync(0xffffffffu, part, 1);
                part += __shfl_xor_sync(0xffffffffu, part, 2);
                if ((lane & 3) == 0) {
                    int row = bm + wm * 32 + mt * 16 + (lane >> 2) + half * 8;
                    sout[((size_t)row * HEADS + head) * 2 + slot] = part;
                }
            }
        }
    }
}

// ---------------- NT GEMM via bf16x3 mma, symmetric (R6-proven) ----------------
__global__ __launch_bounds__(512) void k_dot_mma(
    const __nv_bfloat16* __restrict__ Ehi, const __nv_bfloat16* __restrict__ Elo,
    float* __restrict__ C) {
    __shared__ __nv_bfloat16 sA[2][2][128 * DSTRIDE];
    __shared__ __nv_bfloat16 sB[2][2][128 * DSTRIDE];
    int tid = threadIdx.x;
    int lane = tid & 31, wid = tid >> 5;
    int wm = wid >> 2, wn = wid & 3;

    int bid = blockIdx.x;
    int brow = (int)((sqrtf(8.0f * (float)bid + 1.0f) - 1.0f) * 0.5f);
    while ((brow + 1) * (brow + 2) / 2 <= bid) brow++;
    while (brow * (brow + 1) / 2 > bid) brow--;
    int bcol = bid - brow * (brow + 1) / 2;
    int bi = brow * 128, bj = bcol * 128;  // bi >= bj

    int grow = tid >> 2;
    int gcol = (tid & 3) * 4;
    const __nv_bfloat16* pAhi = Ehi + (size_t)(bi + grow) * EMBD + gcol;
    const __nv_bfloat16* pAlo = Elo + (size_t)(bi + grow) * EMBD + gcol;
    const __nv_bfloat16* pBhi = Ehi + (size_t)(bj + grow) * EMBD + gcol;
    const __nv_bfloat16* pBlo = Elo + (size_t)(bj + grow) * EMBD + gcol;
    int soff = grow * DSTRIDE + gcol;

    int lrow = (lane & 7) + ((lane >> 3) & 1) * 8;
    int lcol = (lane >> 4) * 8;

    float acc[2][4][4];
#pragma unroll
    for (int m = 0; m < 2; m++)
#pragma unroll
        for (int n = 0; n < 4; n++)
#pragma unroll
            for (int q = 0; q < 4; q++) acc[m][n][q] = 0.f;

    uint2 vah = *(const uint2*)pAhi;
    uint2 val = *(const uint2*)pAlo;
    uint2 vbh = *(const uint2*)pBhi;
    uint2 vbl = *(const uint2*)pBlo;
    *(uint2*)&sA[0][0][soff] = vah;
    *(uint2*)&sA[0][1][soff] = val;
    *(uint2*)&sB[0][0][soff] = vbh;
    *(uint2*)&sB[0][1][soff] = vbl;
    vah = *(const uint2*)(pAhi + 16);
    val = *(const uint2*)(pAlo + 16);
    vbh = *(const uint2*)(pBhi + 16);
    vbl = *(const uint2*)(pBlo + 16);
    __syncthreads();

    for (int it = 0; it < EMBD / 16; it++) {
        int st = it & 1;
        uint32_t fa[2][2][4], fb[2][2][4];
#pragma unroll
        for (int mt = 0; mt < 2; mt++)
#pragma unroll
            for (int op = 0; op < 2; op++) {
                uint32_t ad = (uint32_t)__cvta_generic_to_shared(
                    &sA[st][op][(wm * 32 + mt * 16 + lrow) * DSTRIDE + lcol]);
                LDSM4(fa[mt][op], ad);
            }
#pragma unroll
        for (int np = 0; np < 2; np++)
#pragma unroll
            for (int op = 0; op < 2; op++) {
                uint32_t ad = (uint32_t)__cvta_generic_to_shared(
                    &sB[st][op][(wn * 32 + np * 16 + lrow) * DSTRIDE + lcol]);
                LDSM4(fb[np][op], ad);
            }
        if (it < EMBD / 16 - 1) {
            int ns = st ^ 1;
            *(uint2*)&sA[ns][0][soff] = vah;
            *(uint2*)&sA[ns][1][soff] = val;
            *(uint2*)&sB[ns][0][soff] = vbh;
            *(uint2*)&sB[ns][1][soff] = vbl;
        }
        __syncthreads();
        if (it < EMBD / 16 - 2) {
            vah = *(const uint2*)(pAhi + (it + 2) * 16);
            val = *(const uint2*)(pAlo + (it + 2) * 16);
            vbh = *(const uint2*)(pBhi + (it + 2) * 16);
            vbl = *(const uint2*)(pBlo + (it + 2) * 16);
        }
#pragma unroll
        for (int mt = 0; mt < 2; mt++)
#pragma unroll
            for (int np = 0; np < 2; np++)
#pragma unroll
                for (int s = 0; s < 2; s++) {
                    int nt = np * 2 + s;
                    MMA16816(acc[mt][nt], fa[mt][0], fb[np][0][s], fb[np][0][2 + s]);
                    MMA16816(acc[mt][nt], fa[mt][0], fb[np][1][s], fb[np][1][2 + s]);
                    MMA16816(acc[mt][nt], fa[mt][1], fb[np][0][s], fb[np][0][2 + s]);
                }
    }

#pragma unroll
    for (int mt = 0; mt < 2; mt++) {
        int r0 = bi + wm * 32 + mt * 16 + (lane >> 2);
#pragma unroll
        for (int nt = 0; nt < 4; nt++) {
            int cc = bj + wn * 32 + nt * 8 + (lane & 3) * 2;
            float2 v0 = {acc[mt][nt][0], acc[mt][nt][1]};
            float2 v1 = {acc[mt][nt][2], acc[mt][nt][3]};
            *(float2*)(C + (size_t)r0 * BB + cc) = v0;
            *(float2*)(C + (size_t)(r0 + 8) * BB + cc) = v1;
            if (bi != bj) {
                C[(size_t)cc * BB + r0] = acc[mt][nt][0];
                C[(size_t)(cc + 1) * BB + r0] = acc[mt][nt][1];
                C[(size_t)cc * BB + r0 + 8] = acc[mt][nt][2];
                C[(size_t)(cc + 1) * BB + r0 + 8] = acc[mt][nt][3];
            }
        }
    }
}

// all-mods skip + interpolation accumulate -> bf16 hi/lo; also writes weights out
__global__ void k_accum_all(const float* __restrict__ out0, size_t strO,
                            const int* __restrict__ res,
                            const float* __restrict__ gat1, size_t strG,
                            const float* __restrict__ masks,
                            const float* __restrict__ iw,
                            __nv_bfloat16* __restrict__ ahi,
                            __nv_bfloat16* __restrict__ alo,
                            float* __restrict__ wout) {
    int b = blockIdx.x;
    int t = threadIdx.x;
    __shared__ float coef[MODS];
    __shared__ int rid[MODS];
    if (t < MODS) {
        float w0 = iw[0], w1 = iw[1], w2 = iw[2];
        float mw = fmaxf(w0, fmaxf(w1, w2));
        float e0 = expf(w0 - mw), e1 = expf(w1 - mw), e2 = expf(w2 - mw);
        float ws = e0 + e1 + e2;
        float wi = (t == 0 ? e0 : (t == 1 ? e1 : e2)) / ws;
        if (b == 0) wout[t] = wi;
        float m0 = masks[b * 3 + 0], m1 = masks[b * 3 + 1], m2 = masks[b * 3 + 2];
        float msum = m0 + m1 + m2;
        float r = 1.0f + 1.0f / powf(4.0f, 20.0f) + 1.0f / powf(msum, 20.0f);
        r = floorf(r);
        r = r / (r + 1e-10f);
        float z0 = m0 * r, z1 = m1 * r, z2 = m2 * r;
        z0 = z0 + (1.0f - z0) * (-1e10f);
        z1 = z1 + (1.0f - z1) * (-1e10f);
        z2 = z2 + (1.0f - z2) * (-1e10f);
        float zm = fmaxf(z0, fmaxf(z1, z2));
        float x0 = expf(z0 - zm), x1 = expf(z1 - zm), x2 = expf(z2 - zm);
        float xs = x0 + x1 + x2;
        float im = (t == 0 ? x0 : (t == 1 ? x1 : x2)) / xs;
        coef[t] = wi * im;
        rid[t] = res[(size_t)t * BB + b];
    }
    __syncthreads();
    float v = 0.f;
#pragma unroll
    for (int m = 0; m < MODS; m++)
        v += coef[m] * (out0[(size_t)m * strO + (size_t)rid[m] * HID + t] +
                        gat1[(size_t)m * strG + (size_t)b * HID + t]);
    size_t p = (size_t)b * HID + t;
    __nv_bfloat16 hb = __float2bfloat16(v);
    ahi[p] = hb;
    alo[p] = __float2bfloat16(v - __bfloat162float(hb));
}

extern "C" void kernel_launch(void* const* d_in, const int* in_sizes, int n_in,
                              void* d_out, int out_size) {
    const int*   n_id     = (const int*)d_in[0];
    const int*   src0     = (const int*)d_in[1];
    const int*   dst0     = (const int*)d_in[2];
    const int*   src1     = (const int*)d_in[3];
    const int*   dst1     = (const int*)d_in[4];
    const int*   res_n_id = (const int*)d_in[5];
    const float* vals0    = (const float*)d_in[6];
    const float* vals1    = (const float*)d_in[7];
    const float* masks    = (const float*)d_in[8];
    const float* pre_W    = (const float*)d_in[9];
    const float* pre_b    = (const float*)d_in[10];
    const float* W_gat    = (const float*)d_in[11];
    const float* att      = (const float*)d_in[12];
    const float* gat_b    = (const float*)d_in[13];
    const float* interp_w = (const float*)d_in[14];
    const float* emb_W    = (const float*)d_in[15];
    const float* emb_b    = (const float*)d_in[16];

    float* dot = (float*)d_out;
    float* emb = dot + (size_t)BB * BB;
    float* wout = emb + (size_t)BB * EMBD;

    float *h, *s, *out0, *gat1, *c;
    int *cnt, *indptr, *wp, *order, *blksum;
    __nv_bfloat16 *ehi, *elo, *pwhi, *pwlo, *wghi, *wglo, *ewhi, *ewlo;
    __nv_bfloat16 *o0hi, *o0lo, *achi, *aclo;
    cudaGetSymbolAddress((void**)&h, g_h);
    cudaGetSymbolAddress((void**)&s, g_s);
    cudaGetSymbolAddress((void**)&out0, g_out0);
    cudaGetSymbolAddress((void**)&gat1, g_gat1);
    cudaGetSymbolAddress((void**)&c, g_c);
    cudaGetSymbolAddress((void**)&cnt, g_cnt);
    cudaGetSymbolAddress((void**)&indptr, g_indptr);
    cudaGetSymbolAddress((void**)&wp, g_wp);
    cudaGetSymbolAddress((void**)&order, g_order);
    cudaGetSymbolAddress((void**)&blksum, g_blksum);
    cudaGetSymbolAddress((void**)&ehi, g_ehi);
    cudaGetSymbolAddress((void**)&elo, g_elo);
    cudaGetSymbolAddress((void**)&pwhi, g_pwhi);
    cudaGetSymbolAddress((void**)&pwlo, g_pwlo);
    cudaGetSymbolAddress((void**)&wghi, g_wghi);
    cudaGetSymbolAddress((void**)&wglo, g_wglo);
    cudaGetSymbolAddress((void**)&ewhi, g_ewhi);
    cudaGetSymbolAddress((void**)&ewlo, g_ewlo);
    cudaGetSymbolAddress((void**)&o0hi, g_o0hi);
    cudaGetSymbolAddress((void**)&o0lo, g_o0lo);
    cudaGetSymbolAddress((void**)&achi, g_achi);
    cudaGetSymbolAddress((void**)&aclo, g_aclo);

    // ---- streams/events: created AND destroyed within this call ----
    cudaStream_t st[MODS], stCSR;
    st[0] = 0;
    cudaStreamCreateWithFlags(&st[1], cudaStreamNonBlocking);
    cudaStreamCreateWithFlags(&st[2], cudaStreamNonBlocking);
    cudaStreamCreateWithFlags(&stCSR, cudaStreamNonBlocking);
    cudaEvent_t evFork0, evSplit, evCSR, evEW, evJoin1, evJoin2;
    cudaEventCreateWithFlags(&evFork0, cudaEventDisableTiming);
    cudaEventCreateWithFlags(&evSplit, cudaEventDisableTiming);
    cudaEventCreateWithFlags(&evCSR, cudaEventDisableTiming);
    cudaEventCreateWithFlags(&evEW, cudaEventDisableTiming);
    cudaEventCreateWithFlags(&evJoin1, cudaEventDisableTiming);
    cudaEventCreateWithFlags(&evJoin2, cudaEventDisableTiming);

    // fork CSR stream at capture start (CSR independent of splits)
    cudaEventRecord(evFork0, 0);
    cudaStreamWaitEvent(stCSR, evFork0, 0);

    // ---- CSR build + emb_W split on stCSR (overlaps splits + chains) ----
    k_zero_i<<<(TSEG + 255) / 256, 256, 0, stCSR>>>(cnt, TSEG);
    k_hist_all<<<(TEDG + 255) / 256, 256, 0, stCSR>>>(dst0, dst1, cnt);
    k_scan1<<<NSCANB, 1024, 0, stCSR>>>(cnt, TSEG, indptr, blksum);
    k_scan2<<<1, 128, 0, stCSR>>>(blksum, NSCANB, indptr, TSEG);
    k_scan3<<<(TSEG + 255) / 256, 256, 0, stCSR>>>(indptr, wp, blksum, TSEG);
    k_scatter_all<<<(TEDG + 255) / 256, 256, 0, stCSR>>>(dst0, dst1, wp, order);
    k_sortseg<<<(TSEG + 255) / 256, 256, 0, stCSR>>>(indptr, TSEG, order);
    cudaEventRecord(evCSR, stCSR);
    k_split<<<(HID * EMBD / 4 + 255) / 256, 256, 0, stCSR>>>(emb_W, ewhi, ewlo,
                                                             HID * EMBD);
    cudaEventRecord(evEW, stCSR);

    // ---- operand pre-split on stream 0 (R14-proven arrangement) ----
    {
        size_t npw = (size_t)MODS * INSZ * HID;
        k_split_pw<<<(unsigned)((npw / 4 + 255) / 256), 256>>>(pre_W, pre_b, pwhi, pwlo);
        k_split<<<(MODS * HID * HID / 4 + 255) / 256, 256>>>(W_gat, wghi, wglo,
                                                             MODS * HID * HID);
    }
    cudaEventRecord(evSplit, 0);
    cudaStreamWaitEvent(st[1], evSplit, 0);
    cudaStreamWaitEvent(st[2], evSplit, 0);

    // ---- 3 independent modality chains on 3 streams ----
    for (int i = 0; i < MODS; i++) {
        cudaStream_t sm = st[i];
        const float* ai  = att + (size_t)i * HID;
        const float* gbi = gat_b + (size_t)i * HID;
        const int* ip0 = indptr + i * (NN1 + BB);
        const int* ip1 = indptr + i * (NN1 + BB) + NN1;
        float* h_i = h + (size_t)i * NN0 * HID;
        float* s_i = s + (size_t)i * NN0 * HEADS * 2;
        float* c_i = c + (size_t)i * EE0 * HEADS;
        float* out0_i = out0 + (size_t)i * NN1 * HID;
        float* gat1_i = gat1 + (size_t)i * BB * HID;
        const __nv_bfloat16* wghi_i = wghi + (size_t)i * HID * HID;
        const __nv_bfloat16* wglo_i = wglo + (size_t)i * HID * HID;

        // block 0: GEMM first (doesn't need CSR), then wait CSR for coef
        const int* s0 = src0 + (size_t)i * EE0;
        {
            dim3 grid(HID / 128, NN0 / 128);
            k_gemm_bf<<<grid, 512, 0, sm>>>(pwhi + (size_t)i * INSZ * HID,
                                            pwlo + (size_t)i * INSZ * HID,
                                            n_id + (size_t)i * NN0,
                                            wghi_i, wglo_i, nullptr, h_i,
                                            NN0, HID, HID, nullptr, nullptr, ai, s_i);
        }
        cudaStreamWaitEvent(sm, evCSR, 0);
        k_coef<<<(NN1 * 32 + 255) / 256, 256, 0, sm>>>(
            order, ip0, s0, vals0 + (size_t)i * EE0, s_i, c_i, NN1);
        k_reduce<<<NN1, 256, 0, sm>>>(order, ip0, s0, c_i, h_i, gbi, out0_i,
                                      o0hi + (size_t)i * NN1 * HID,
                                      o0lo + (size_t)i * NN1 * HID);

        // block 1
        const int* s1 = src1 + (size_t)i * EE1;
        {
            dim3 grid(HID / 128, NN1 / 128);
            k_gemm_bf<<<grid, 512, 0, sm>>>(o0hi + (size_t)i * NN1 * HID,
                                            o0lo + (size_t)i * NN1 * HID,
                                            nullptr, wghi_i, wglo_i, nullptr, h_i,
                                            NN1, HID, HID, nullptr, nullptr, ai, s_i);
        }
        k_coef<<<(BB * 32 + 255) / 256, 256, 0, sm>>>(
            order, ip1, s1, vals1 + (size_t)i * EE1, s_i, c_i, BB);
        k_reduce<<<BB, 256, 0, sm>>>(order, ip1, s1, c_i, h_i, gbi, gat1_i,
                                     nullptr, nullptr);
    }

    cudaEventRecord(evJoin1, st[1]);
    cudaEventRecord(evJoin2, st[2]);
    cudaStreamWaitEvent(0, evJoin1, 0);
    cudaStreamWaitEvent(0, evJoin2, 0);
    cudaStreamWaitEvent(0, evEW, 0);

    // skip + interpolation accumulate -> bf16 hi/lo (+ fused weights output)
    k_accum_all<<<BB, 256>>>(out0, (size_t)NN1 * HID, res_n_id,
                             gat1, (size_t)BB * HID, masks, interp_w,
                             achi, aclo, wout);

    // emb = acc @ emb_W + emb_b (+ fused bf16 hi/lo split of output)
    {
        dim3 grid(EMBD / 128, BB / 128);
        k_gemm_bf<<<grid, 512>>>(achi, aclo, nullptr, ewhi, ewlo, emb_b, emb,
                                 BB, EMBD, HID, ehi, elo, nullptr, nullptr);
    }
    // dot = emb @ emb^T via bf16x3 mma, symmetric half-grid
    {
        int npairs = (BB / 128) * (BB / 128 + 1) / 2;  // 2080
        k_dot_mma<<<npairs, 512>>>(ehi, elo, dot);
    }

    // ---- release fork resources (capture has rejoined stream 0) ----
    cudaEventDestroy(evFork0);
    cudaEventDestroy(evSplit);
    cudaEventDestroy(evCSR);
    cudaEventDestroy(evEW);
    cudaEventDestroy(evJoin1);
    cudaEventDestroy(evJoin2);
    cudaStreamDestroy(st[1]);
    cudaStreamDestroy(st[2]);
    cudaStreamDestroy(stCSR);
}